// round 7
// baseline (speedup 1.0000x reference)
#include <cuda_runtime.h>

#define H_IMG 512
#define W_IMG 512
#define NMAX  2048
#define TILE_W 16
#define TILE_H 8
#define TXN   (W_IMG / TILE_W)   /* 32 */
#define TYN   (H_IMG / TILE_H)   /* 64 */
#define NTILES (TXN * TYN)       /* 2048 */
#define CAPN  1024               /* max gaussians per tile list */

#define TWO_PI_F        6.28318530717958647692f
#define LOG2E_F         1.44269504088896340736f
#define LOG2_ALPHA_MIN  -7.99435344f    /* log2(1/255) */
#define ARG_CAP         7.99291016f     /* log2(0.999) - LOG2_ALPHA_MIN */
#define NEG_BIG         -126.0f
#define FEAT_SCALE      0.003921568859f /* 2^LOG2_ALPHA_MIN ~= 1/255 */

// Per-tile fully-gathered gaussian data (written by bin, read by render)
__device__ float4 g_TDa[NTILES][CAPN];  // mx, my, A', B'   (A'=-0.5*log2e*c0 etc)
__device__ float4 g_TDb[NTILES][CAPN];  // C', L', fr', fg'
__device__ float  g_TDc[NTILES][CAPN];  // fb'
__device__ int    g_tile_cnt[NTILES];   // zero at load; render re-zeroes

// One WARP per gaussian: all lanes redundantly compute params (broadcast loads),
// then all 32 lanes cooperatively test candidate tiles and push full param
// structs into per-tile arrays.
__global__ __launch_bounds__(256)
void prep_bin_kernel(const float* __restrict__ xyz,
                     const float* __restrict__ scaling,
                     const float* __restrict__ rot,
                     const float* __restrict__ feat,
                     const float* __restrict__ opac,
                     int N)
{
    int warp = (blockIdx.x * blockDim.x + threadIdx.x) >> 5;
    int lane = threadIdx.x & 31;
    int i = warp;
    if (i >= N) return;

    float theta = (1.0f / (1.0f + expf(-rot[i]))) * TWO_PI_F;
    float s0 = fabsf(scaling[2*i + 0]); s0 *= s0;
    float s1 = fabsf(scaling[2*i + 1]); s1 *= s1;
    float cs = cosf(theta);
    float sn = sinf(theta);

    float a = cs*cs*s0 + sn*sn*s1;
    float b = cs*sn*(s0 - s1);
    float c = sn*sn*s0 + cs*cs*s1;
    float inv_det = 1.0f / (a*c - b*b);
    float c0 =  c * inv_det;
    float c1 = -b * inv_det;
    float c2 =  a * inv_det;

    float mx = 0.5f * ((xyz[2*i + 0] + 1.0f) * (float)W_IMG - 1.0f);
    float my = 0.5f * ((xyz[2*i + 1] + 1.0f) * (float)H_IMG - 1.0f);

    float op = opac[i];
    // arg_b = L' + A'*dx^2 + B'*dy^2 + C'*dx*dy ;  keep iff arg_b >= 0
    // alpha = 2^(arg_b) * 2^LOG2_ALPHA_MIN  (folded into features)
    float Ap = -0.5f * LOG2E_F * c0;
    float Bp = -0.5f * LOG2E_F * c2;
    float Cp = -LOG2E_F * c1;
    float Lp = log2f(op) - LOG2_ALPHA_MIN;

    float lnthr = logf(op * 255.0f);      // contributes iff sigma <= lnthr
    float smax  = fmaxf(s0, s1);          // lambda_max(Sigma) upper bound
    float r2 = (lnthr > 0.0f) ? (2.0f * smax * lnthr) : -1.0f;
    if (r2 <= 0.0f) return;
    float r = sqrtf(r2);

    float4 Pa = make_float4(mx, my, Ap, Bp);
    float4 Pb = make_float4(Cp, Lp, feat[3*i + 0] * FEAT_SCALE,
                                    feat[3*i + 1] * FEAT_SCALE);
    float  Pc = feat[3*i + 2] * FEAT_SCALE;

    int tx_lo = max(0,       (int)floorf((mx - r) * (1.0f / TILE_W)));
    int tx_hi = min(TXN - 1, (int)floorf((mx + r) * (1.0f / TILE_W)));
    int ty_lo = max(0,       (int)floorf((my - r) * (1.0f / TILE_H)));
    int ty_hi = min(TYN - 1, (int)floorf((my + r) * (1.0f / TILE_H)));
    if (tx_hi < tx_lo || ty_hi < ty_lo) return;

    int w = tx_hi - tx_lo + 1;
    int cand = w * (ty_hi - ty_lo + 1);

    for (int sidx = lane; sidx < cand; sidx += 32) {
        int tx = tx_lo + (sidx % w);
        int ty = ty_lo + (sidx / w);
        float bx0 = (float)(tx * TILE_W);
        float by0 = (float)(ty * TILE_H);
        float dxb = fmaxf(0.0f, fmaxf(bx0 - mx, mx - (bx0 + (TILE_W - 1))));
        float dyb = fmaxf(0.0f, fmaxf(by0 - my, my - (by0 + (TILE_H - 1))));
        if (fmaf(dxb, dxb, dyb * dyb) <= r2) {
            int t = ty * TXN + tx;
            int pos = atomicAdd(&g_tile_cnt[t], 1);
            if (pos < CAPN) {
                g_TDa[t][pos] = Pa;
                g_TDb[t][pos] = Pb;
                g_TDc[t][pos] = Pc;
            }
        }
    }
}

// 256 threads = 8 warps = 2 tiles x 4-way gaussian split.
// Each warp renders its FULL 16x8 tile (lane = 2x2 quad: x,x+8 ; y,y+4),
// processing gaussians j = wg, wg+4, ... No per-chunk barriers; one
// fixed-order reduction at the end (deterministic given list order).
__global__ __launch_bounds__(256, 4)
void render_kernel(float* __restrict__ out)
{
    __shared__ float s_red[2][3][32 * 13];   // [tile][pub warp][lane*13 + k]

    const int tid  = threadIdx.x;
    const int w    = tid >> 5;
    const int lane = tid & 31;
    const int tl   = w >> 2;     // tile within CTA: 0/1
    const int wg   = w & 3;      // gaussian-split group 0..3

    const int tile = blockIdx.x * 2 + tl;
    const int tx = tile & (TXN - 1);
    const int ty = tile >> 5;
    const int x0 = tx * TILE_W + (lane & 7);
    const int y0 = ty * TILE_H + (lane >> 3);
    const float fx0 = (float)x0;
    const float fy0 = (float)y0;

    int cnt = g_tile_cnt[tile];
    if (cnt > CAPN) cnt = CAPN;
    __syncthreads();
    if (wg == 0 && lane == 0) g_tile_cnt[tile] = 0;   // leave zeroed

    const float4* __restrict__ Ta = g_TDa[tile];
    const float4* __restrict__ Tb = g_TDb[tile];
    const float*  __restrict__ Tc = g_TDc[tile];

    float a00r = 0.0f, a00g = 0.0f, a00b = 0.0f;   // (x, y)
    float a10r = 0.0f, a10g = 0.0f, a10b = 0.0f;   // (x+8, y)
    float a01r = 0.0f, a01g = 0.0f, a01b = 0.0f;   // (x, y+4)
    float a11r = 0.0f, a11g = 0.0f, a11b = 0.0f;   // (x+8, y+4)

    #pragma unroll 2
    for (int j = wg; j < cnt; j += 4) {
        float4 qa = Ta[j];
        float4 qb = Tb[j];
        float  qc = Tc[j];

        float dx0 = fx0 - qa.x, dx1 = dx0 + 8.0f;
        float dy0 = fy0 - qa.y, dy1 = dy0 + 4.0f;

        float adx0 = qa.z * dx0;                  // A'*dx  (per column)
        float adx1 = qa.z * dx1;
        float rt0  = fmaf(qa.w * dy0, dy0, qb.y); // B'*dy^2 + L'  (per row)
        float rt1  = fmaf(qa.w * dy1, dy1, qb.y);

        float t00 = fmaf(qb.x, dy0, adx0);
        float t10 = fmaf(qb.x, dy0, adx1);
        float t01 = fmaf(qb.x, dy1, adx0);
        float t11 = fmaf(qb.x, dy1, adx1);
        float b00 = fmaf(t00, dx0, rt0);
        float b10 = fmaf(t10, dx1, rt0);
        float b01 = fmaf(t01, dx0, rt1);
        float b11 = fmaf(t11, dx1, rt1);

        b00 = fminf(b00, ARG_CAP);
        b10 = fminf(b10, ARG_CAP);
        b01 = fminf(b01, ARG_CAP);
        b11 = fminf(b11, ARG_CAP);

        // below threshold (arg_b < 0) -> -126 -> ex2 ~ 0 (FTZ kills it)
        float z00, z10, z01, z11;
        asm("slct.f32.f32 %0, %1, %2, %1;" : "=f"(z00) : "f"(b00), "f"(NEG_BIG));
        asm("slct.f32.f32 %0, %1, %2, %1;" : "=f"(z10) : "f"(b10), "f"(NEG_BIG));
        asm("slct.f32.f32 %0, %1, %2, %1;" : "=f"(z01) : "f"(b01), "f"(NEG_BIG));
        asm("slct.f32.f32 %0, %1, %2, %1;" : "=f"(z11) : "f"(b11), "f"(NEG_BIG));

        float e00, e10, e01, e11;
        asm("ex2.approx.ftz.f32 %0, %1;" : "=f"(e00) : "f"(z00));
        asm("ex2.approx.ftz.f32 %0, %1;" : "=f"(e10) : "f"(z10));
        asm("ex2.approx.ftz.f32 %0, %1;" : "=f"(e01) : "f"(z01));
        asm("ex2.approx.ftz.f32 %0, %1;" : "=f"(e11) : "f"(z11));

        a00r = fmaf(e00, qb.z, a00r);
        a00g = fmaf(e00, qb.w, a00g);
        a00b = fmaf(e00, qc,   a00b);
        a10r = fmaf(e10, qb.z, a10r);
        a10g = fmaf(e10, qb.w, a10g);
        a10b = fmaf(e10, qc,   a10b);
        a01r = fmaf(e01, qb.z, a01r);
        a01g = fmaf(e01, qb.w, a01g);
        a01b = fmaf(e01, qc,   a01b);
        a11r = fmaf(e11, qb.z, a11r);
        a11g = fmaf(e11, qb.w, a11g);
        a11b = fmaf(e11, qc,   a11b);
    }

    // warps 1-3 of each tile publish; warp 0 reduces in fixed order
    if (wg > 0) {
        float* dst = &s_red[tl][wg - 1][lane * 13];
        dst[0]  = a00r; dst[1]  = a00g; dst[2]  = a00b;
        dst[3]  = a10r; dst[4]  = a10g; dst[5]  = a10b;
        dst[6]  = a01r; dst[7]  = a01g; dst[8]  = a01b;
        dst[9]  = a11r; dst[10] = a11g; dst[11] = a11b;
    }
    __syncthreads();

    if (wg == 0) {
        #pragma unroll
        for (int gg = 0; gg < 3; ++gg) {
            const float* src = &s_red[tl][gg][lane * 13];
            a00r += src[0];  a00g += src[1];  a00b += src[2];
            a10r += src[3];  a10g += src[4];  a10b += src[5];
            a01r += src[6];  a01g += src[7];  a01b += src[8];
            a11r += src[9];  a11g += src[10]; a11b += src[11];
        }

        const int x1 = x0 + 8;
        const int y1 = y0 + 4;
        // out layout: [1, 3, H, W]
        out[(0 * H_IMG + y0) * W_IMG + x0] = fminf(fmaxf(a00r, 0.0f), 1.0f);
        out[(0 * H_IMG + y0) * W_IMG + x1] = fminf(fmaxf(a10r, 0.0f), 1.0f);
        out[(0 * H_IMG + y1) * W_IMG + x0] = fminf(fmaxf(a01r, 0.0f), 1.0f);
        out[(0 * H_IMG + y1) * W_IMG + x1] = fminf(fmaxf(a11r, 0.0f), 1.0f);
        out[(1 * H_IMG + y0) * W_IMG + x0] = fminf(fmaxf(a00g, 0.0f), 1.0f);
        out[(1 * H_IMG + y0) * W_IMG + x1] = fminf(fmaxf(a10g, 0.0f), 1.0f);
        out[(1 * H_IMG + y1) * W_IMG + x0] = fminf(fmaxf(a01g, 0.0f), 1.0f);
        out[(1 * H_IMG + y1) * W_IMG + x1] = fminf(fmaxf(a11g, 0.0f), 1.0f);
        out[(2 * H_IMG + y0) * W_IMG + x0] = fminf(fmaxf(a00b, 0.0f), 1.0f);
        out[(2 * H_IMG + y0) * W_IMG + x1] = fminf(fmaxf(a10b, 0.0f), 1.0f);
        out[(2 * H_IMG + y1) * W_IMG + x0] = fminf(fmaxf(a01b, 0.0f), 1.0f);
        out[(2 * H_IMG + y1) * W_IMG + x1] = fminf(fmaxf(a11b, 0.0f), 1.0f);
    }
}

extern "C" void kernel_launch(void* const* d_in, const int* in_sizes, int n_in,
                              void* d_out, int out_size)
{
    const float* xyz     = (const float*)d_in[0];
    const float* scaling = (const float*)d_in[1];
    const float* rot     = (const float*)d_in[2];
    const float* feat    = (const float*)d_in[3];
    const float* opac    = (const float*)d_in[4];
    float* out = (float*)d_out;

    int N = in_sizes[0] / 2;
    if (N > NMAX) N = NMAX;

    // one warp per gaussian
    prep_bin_kernel<<<(N * 32 + 255) / 256, 256>>>(xyz, scaling, rot, feat, opac, N);

    // 2 tiles per CTA
    render_kernel<<<NTILES / 2, 256>>>(out);
}

// round 8
// speedup vs baseline: 1.2220x; 1.2220x over previous
#include <cuda_runtime.h>

#define H_IMG 512
#define W_IMG 512
#define NMAX  2048
#define TILE  16
#define TX_N  (W_IMG / TILE)   /* 32 */
#define TY_N  (H_IMG / TILE)   /* 32 */
#define NTILES (TX_N * TY_N)   /* 1024 */
#define CHUNK 256

#define TWO_PI_F        6.28318530717958647692f
#define LOG2E_F         1.44269504088896340736f
#define LOG2_ALPHA_MIN  -7.99435344f    /* log2(1/255) */
#define ARG_CAP         7.99291016f     /* log2(0.999) - LOG2_ALPHA_MIN */
#define NEG_BIG         -126.0f
#define FEAT_SCALE      0.003921568859f /* 2^LOG2_ALPHA_MIN = 1/255 */

// Per-gaussian precomputed parameters (pre-scaled: see prep)
__device__ float4 g_P0[NMAX];          // mx, my, A'(=-0.5*log2e*c0), B'(=-0.5*log2e*c2)
__device__ float4 g_P1[NMAX];          // C'(=-log2e*c1), L'(=log2(op)-LOG2_ALPHA_MIN), fr', fg'
__device__ float  g_FB[NMAX];          // fb'
// Per-tile gaussian index lists
__device__ int    g_tile_cnt[NTILES];          // zero at load; render re-zeroes
__device__ int    g_tile_list[NTILES][NMAX];   // 8 MB static scratch

// One WARP per gaussian: all lanes redundantly compute params (broadcast loads),
// lane 0 writes them, then all 32 lanes cooperatively test candidate tiles.
__global__ __launch_bounds__(256)
void prep_bin_kernel(const float* __restrict__ xyz,
                     const float* __restrict__ scaling,
                     const float* __restrict__ rot,
                     const float* __restrict__ feat,
                     const float* __restrict__ opac,
                     int N)
{
    int warp = (blockIdx.x * blockDim.x + threadIdx.x) >> 5;
    int lane = threadIdx.x & 31;
    int i = warp;
    if (i >= N) return;

    float theta = (1.0f / (1.0f + expf(-rot[i]))) * TWO_PI_F;
    float s0 = fabsf(scaling[2*i + 0]); s0 *= s0;
    float s1 = fabsf(scaling[2*i + 1]); s1 *= s1;
    float cs = cosf(theta);
    float sn = sinf(theta);

    float a = cs*cs*s0 + sn*sn*s1;
    float b = cs*sn*(s0 - s1);
    float c = sn*sn*s0 + cs*cs*s1;
    float inv_det = 1.0f / (a*c - b*b);
    float c0 =  c * inv_det;
    float c1 = -b * inv_det;
    float c2 =  a * inv_det;

    float mx = 0.5f * ((xyz[2*i + 0] + 1.0f) * (float)W_IMG - 1.0f);
    float my = 0.5f * ((xyz[2*i + 1] + 1.0f) * (float)H_IMG - 1.0f);

    float op = opac[i];
    // arg = L' + A'*dx^2 + B'*dy^2 + C'*dx*dy ; contributes iff arg >= 0
    // alpha = 2^(arg + LOG2_ALPHA_MIN); the 2^LOG2_ALPHA_MIN folded into features
    if (lane == 0) {
        g_P0[i] = make_float4(mx, my, -0.5f * LOG2E_F * c0, -0.5f * LOG2E_F * c2);
        g_P1[i] = make_float4(-LOG2E_F * c1, log2f(op) - LOG2_ALPHA_MIN,
                              feat[3*i + 0] * FEAT_SCALE, feat[3*i + 1] * FEAT_SCALE);
        g_FB[i] = feat[3*i + 2] * FEAT_SCALE;
    }

    float lnthr = logf(op * 255.0f);      // contributes iff sigma <= lnthr
    float smax  = fmaxf(s0, s1);          // lambda_max(Sigma) upper bound
    float r2 = (lnthr > 0.0f) ? (2.0f * smax * lnthr) : -1.0f;
    if (r2 <= 0.0f) return;
    float r = sqrtf(r2);

    int tx_lo = max(0,        (int)floorf((mx - r) * (1.0f / TILE)));
    int tx_hi = min(TX_N - 1, (int)floorf((mx + r) * (1.0f / TILE)));
    int ty_lo = max(0,        (int)floorf((my - r) * (1.0f / TILE)));
    int ty_hi = min(TY_N - 1, (int)floorf((my + r) * (1.0f / TILE)));
    if (tx_hi < tx_lo || ty_hi < ty_lo) return;

    int w = tx_hi - tx_lo + 1;
    int cand = w * (ty_hi - ty_lo + 1);

    for (int sidx = lane; sidx < cand; sidx += 32) {
        int tx = tx_lo + (sidx % w);
        int ty = ty_lo + (sidx / w);
        float bx0 = (float)(tx * TILE);
        float by0 = (float)(ty * TILE);
        float dxb = fmaxf(0.0f, fmaxf(bx0 - mx, mx - (bx0 + (TILE - 1))));
        float dyb = fmaxf(0.0f, fmaxf(by0 - my, my - (by0 + (TILE - 1))));
        if (fmaf(dxb, dxb, dyb * dyb) <= r2) {
            int t = ty * TX_N + tx;
            int pos = atomicAdd(&g_tile_cnt[t], 1);
            g_tile_list[t][pos] = i;
        }
    }
}

// 64 threads/CTA, each thread renders a 2x2 quad at stride 8:
// (px, py), (px+8, py), (px, py+8), (px+8, py+8).
// Params staged in shared per chunk; deep unroll for ILP.
__global__ __launch_bounds__(64, 8)
void render_kernel(float* __restrict__ out)
{
    __shared__ float4 sP0[CHUNK];
    __shared__ float4 sP1[CHUNK];
    __shared__ float  sFB[CHUNK];

    const int tid = threadIdx.x;
    const int tx  = tid & 7;             // 0..7
    const int ty  = tid >> 3;            // 0..7

    const int tile = blockIdx.y * TX_N + blockIdx.x;
    const int px0 = blockIdx.x * TILE + tx;
    const int py0 = blockIdx.y * TILE + ty;
    const float fx0 = (float)px0;
    const float fy0 = (float)py0;

    const int cnt = g_tile_cnt[tile];

    float a00r = 0.0f, a00g = 0.0f, a00b = 0.0f;   // (x, y)
    float a10r = 0.0f, a10g = 0.0f, a10b = 0.0f;   // (x+8, y)
    float a01r = 0.0f, a01g = 0.0f, a01b = 0.0f;   // (x, y+8)
    float a11r = 0.0f, a11g = 0.0f, a11b = 0.0f;   // (x+8, y+8)

    for (int base = 0; base < cnt; base += CHUNK) {
        int m = cnt - base;
        if (m > CHUNK) m = CHUNK;

        for (int k2 = tid; k2 < m; k2 += 64) {
            int g = g_tile_list[tile][base + k2];
            sP0[k2] = g_P0[g];
            sP1[k2] = g_P1[g];
            sFB[k2] = g_FB[g];
        }
        __syncthreads();

        #pragma unroll 4
        for (int j = 0; j < m; ++j) {
            float4 qa = sP0[j];
            float4 qb = sP1[j];
            float  qc = sFB[j];

            float dx0 = fx0 - qa.x, dx1 = dx0 + 8.0f;
            float dy0 = fy0 - qa.y, dy1 = dy0 + 8.0f;

            float adx0 = qa.z * dx0;                  // A'*dx  (per column)
            float adx1 = qa.z * dx1;
            float rt0  = fmaf(qa.w * dy0, dy0, qb.y); // B'*dy^2 + L'  (per row)
            float rt1  = fmaf(qa.w * dy1, dy1, qb.y);

            float t00 = fmaf(qb.x, dy0, adx0);
            float t10 = fmaf(qb.x, dy0, adx1);
            float t01 = fmaf(qb.x, dy1, adx0);
            float t11 = fmaf(qb.x, dy1, adx1);
            float b00 = fmaf(t00, dx0, rt0);
            float b10 = fmaf(t10, dx1, rt0);
            float b01 = fmaf(t01, dx0, rt1);
            float b11 = fmaf(t11, dx1, rt1);

            b00 = fminf(b00, ARG_CAP);
            b10 = fminf(b10, ARG_CAP);
            b01 = fminf(b01, ARG_CAP);
            b11 = fminf(b11, ARG_CAP);

            // arg < 0 (alpha below 1/255) -> -126 -> ex2 flushes to 0
            float z00, z10, z01, z11;
            asm("slct.f32.f32 %0, %1, %2, %1;" : "=f"(z00) : "f"(b00), "f"(NEG_BIG));
            asm("slct.f32.f32 %0, %1, %2, %1;" : "=f"(z10) : "f"(b10), "f"(NEG_BIG));
            asm("slct.f32.f32 %0, %1, %2, %1;" : "=f"(z01) : "f"(b01), "f"(NEG_BIG));
            asm("slct.f32.f32 %0, %1, %2, %1;" : "=f"(z11) : "f"(b11), "f"(NEG_BIG));

            float e00, e10, e01, e11;
            asm("ex2.approx.ftz.f32 %0, %1;" : "=f"(e00) : "f"(z00));
            asm("ex2.approx.ftz.f32 %0, %1;" : "=f"(e10) : "f"(z10));
            asm("ex2.approx.ftz.f32 %0, %1;" : "=f"(e01) : "f"(z01));
            asm("ex2.approx.ftz.f32 %0, %1;" : "=f"(e11) : "f"(z11));

            a00r = fmaf(e00, qb.z, a00r);
            a00g = fmaf(e00, qb.w, a00g);
            a00b = fmaf(e00, qc,   a00b);
            a10r = fmaf(e10, qb.z, a10r);
            a10g = fmaf(e10, qb.w, a10g);
            a10b = fmaf(e10, qc,   a10b);
            a01r = fmaf(e01, qb.z, a01r);
            a01g = fmaf(e01, qb.w, a01g);
            a01b = fmaf(e01, qc,   a01b);
            a11r = fmaf(e11, qb.z, a11r);
            a11g = fmaf(e11, qb.w, a11g);
            a11b = fmaf(e11, qc,   a11b);
        }
        __syncthreads();
    }

    if (tid == 0) g_tile_cnt[tile] = 0;   // leave zeroed for next launch

    const int px1 = px0 + 8;
    const int py1 = py0 + 8;
    // out layout: [1, 3, H, W]
    out[(0 * H_IMG + py0) * W_IMG + px0] = fminf(fmaxf(a00r, 0.0f), 1.0f);
    out[(0 * H_IMG + py0) * W_IMG + px1] = fminf(fmaxf(a10r, 0.0f), 1.0f);
    out[(0 * H_IMG + py1) * W_IMG + px0] = fminf(fmaxf(a01r, 0.0f), 1.0f);
    out[(0 * H_IMG + py1) * W_IMG + px1] = fminf(fmaxf(a11r, 0.0f), 1.0f);
    out[(1 * H_IMG + py0) * W_IMG + px0] = fminf(fmaxf(a00g, 0.0f), 1.0f);
    out[(1 * H_IMG + py0) * W_IMG + px1] = fminf(fmaxf(a10g, 0.0f), 1.0f);
    out[(1 * H_IMG + py1) * W_IMG + px0] = fminf(fmaxf(a01g, 0.0f), 1.0f);
    out[(1 * H_IMG + py1) * W_IMG + px1] = fminf(fmaxf(a11g, 0.0f), 1.0f);
    out[(2 * H_IMG + py0) * W_IMG + px0] = fminf(fmaxf(a00b, 0.0f), 1.0f);
    out[(2 * H_IMG + py0) * W_IMG + px1] = fminf(fmaxf(a10b, 0.0f), 1.0f);
    out[(2 * H_IMG + py1) * W_IMG + px0] = fminf(fmaxf(a01b, 0.0f), 1.0f);
    out[(2 * H_IMG + py1) * W_IMG + px1] = fminf(fmaxf(a11b, 0.0f), 1.0f);
}

extern "C" void kernel_launch(void* const* d_in, const int* in_sizes, int n_in,
                              void* d_out, int out_size)
{
    const float* xyz     = (const float*)d_in[0];
    const float* scaling = (const float*)d_in[1];
    const float* rot     = (const float*)d_in[2];
    const float* feat    = (const float*)d_in[3];
    const float* opac    = (const float*)d_in[4];
    float* out = (float*)d_out;

    int N = in_sizes[0] / 2;
    if (N > NMAX) N = NMAX;

    // one warp per gaussian
    prep_bin_kernel<<<(N * 32 + 255) / 256, 256>>>(xyz, scaling, rot, feat, opac, N);

    dim3 grid(TX_N, TY_N);
    render_kernel<<<grid, 64>>>(out);
}

// round 9
// speedup vs baseline: 1.2484x; 1.0216x over previous
#include <cuda_runtime.h>

#define H_IMG 512
#define W_IMG 512
#define NMAX  2048
#define TILE  16
#define TX_N  (W_IMG / TILE)   /* 32 */
#define TY_N  (H_IMG / TILE)   /* 32 */
#define NTILES (TX_N * TY_N)   /* 1024 */
#define CHUNK 256

#define TWO_PI_F        6.28318530717958647692f
#define LOG2E_F         1.44269504088896340736f
#define LOG2_ALPHA_MIN  -7.99435344f    /* log2(1/255) */
#define E_CAP           254.745f        /* 0.999 * 255 */
#define FEAT_SCALE      0.003921568859f /* 1/255 */

// Per-gaussian precomputed parameters (pre-scaled)
__device__ float4 g_P0[NMAX];   // mx, my, A'(=-0.5*log2e*c0), B'(=-0.5*log2e*c2)
__device__ float4 g_P1[NMAX];   // C'(=-log2e*c1), L'(=log2(op)-LOG2_ALPHA_MIN), fr', fg'
__device__ float  g_FB[NMAX];   // fb'
// Per-tile gaussian index lists
__device__ int    g_tile_cnt[NTILES];          // zero at load; render re-zeroes
__device__ int    g_tile_list[NTILES][NMAX];   // 8 MB static scratch

// One WARP per gaussian. Candidate tiles from the (loose) disk bbox, then an
// EXACT ellipse-vs-box test: min of the positive-definite quadratic sigma over
// the tile box (0 if center inside, else min over the 4 edges by convexity).
__global__ __launch_bounds__(256)
void prep_bin_kernel(const float* __restrict__ xyz,
                     const float* __restrict__ scaling,
                     const float* __restrict__ rot,
                     const float* __restrict__ feat,
                     const float* __restrict__ opac,
                     int N)
{
    int warp = (blockIdx.x * blockDim.x + threadIdx.x) >> 5;
    int lane = threadIdx.x & 31;
    int i = warp;
    if (i >= N) return;

    float theta = (1.0f / (1.0f + expf(-rot[i]))) * TWO_PI_F;
    float s0 = fabsf(scaling[2*i + 0]); s0 *= s0;
    float s1 = fabsf(scaling[2*i + 1]); s1 *= s1;
    float cs = cosf(theta);
    float sn = sinf(theta);

    float a = cs*cs*s0 + sn*sn*s1;
    float b = cs*sn*(s0 - s1);
    float c = sn*sn*s0 + cs*cs*s1;
    float inv_det = 1.0f / (a*c - b*b);
    float c0 =  c * inv_det;
    float c1 = -b * inv_det;
    float c2 =  a * inv_det;

    float mx = 0.5f * ((xyz[2*i + 0] + 1.0f) * (float)W_IMG - 1.0f);
    float my = 0.5f * ((xyz[2*i + 1] + 1.0f) * (float)H_IMG - 1.0f);

    float op = opac[i];
    if (lane == 0) {
        g_P0[i] = make_float4(mx, my, -0.5f * LOG2E_F * c0, -0.5f * LOG2E_F * c2);
        g_P1[i] = make_float4(-LOG2E_F * c1, log2f(op) - LOG2_ALPHA_MIN,
                              feat[3*i + 0] * FEAT_SCALE, feat[3*i + 1] * FEAT_SCALE);
        g_FB[i] = feat[3*i + 2] * FEAT_SCALE;
    }

    float lnthr = logf(op * 255.0f);      // contributes iff sigma <= lnthr
    if (lnthr <= 0.0f) return;
    float thr = lnthr + 1e-2f;            // safety margin >> fp-order noise

    // sigma(d) = aq*dx^2 + bq*dx*dy + cq*dy^2  (positive definite)
    float aq = 0.5f * c0;
    float bq = c1;
    float cq = 0.5f * c2;
    float inv2aq = 0.5f / aq;
    float inv2cq = 0.5f / cq;

    // loose disk bbox for candidate enumeration
    float smax = fmaxf(s0, s1);
    float r = sqrtf(2.0f * smax * lnthr);

    int tx_lo = max(0,        (int)floorf((mx - r) * (1.0f / TILE)));
    int tx_hi = min(TX_N - 1, (int)floorf((mx + r) * (1.0f / TILE)));
    int ty_lo = max(0,        (int)floorf((my - r) * (1.0f / TILE)));
    int ty_hi = min(TY_N - 1, (int)floorf((my + r) * (1.0f / TILE)));
    if (tx_hi < tx_lo || ty_hi < ty_lo) return;

    int w = tx_hi - tx_lo + 1;
    int cand = w * (ty_hi - ty_lo + 1);

    for (int sidx = lane; sidx < cand; sidx += 32) {
        int tx = tx_lo + (sidx % w);
        int ty = ty_lo + (sidx / w);
        // box relative to center
        float lx = (float)(tx * TILE) - mx;
        float hx = lx + (float)(TILE - 1);
        float ly = (float)(ty * TILE) - my;
        float hy = ly + (float)(TILE - 1);

        float smin;
        if (lx <= 0.0f && hx >= 0.0f && ly <= 0.0f && hy >= 0.0f) {
            smin = 0.0f;   // center inside box
        } else {
            // min over each of the 4 edges (clamped 1D quadratic minima)
            // edge x = lx:
            float dyc = fminf(fmaxf(-bq * lx * inv2cq, ly), hy);
            float e0 = fmaf(cq * dyc, dyc, fmaf(bq * lx, dyc, aq * lx * lx));
            // edge x = hx:
            dyc = fminf(fmaxf(-bq * hx * inv2cq, ly), hy);
            float e1 = fmaf(cq * dyc, dyc, fmaf(bq * hx, dyc, aq * hx * hx));
            // edge y = ly:
            float dxc = fminf(fmaxf(-bq * ly * inv2aq, lx), hx);
            float e2 = fmaf(aq * dxc, dxc, fmaf(bq * ly, dxc, cq * ly * ly));
            // edge y = hy:
            dxc = fminf(fmaxf(-bq * hy * inv2aq, lx), hx);
            float e3 = fmaf(aq * dxc, dxc, fmaf(bq * hy, dxc, cq * hy * hy));
            smin = fminf(fminf(e0, e1), fminf(e2, e3));
        }

        if (smin <= thr) {
            int t = ty * TX_N + tx;
            int pos = atomicAdd(&g_tile_cnt[t], 1);
            g_tile_list[t][pos] = i;
        }
    }
}

// 64 threads/CTA, each thread renders a 2x2 quad at stride 8 (R4 structure).
__global__ __launch_bounds__(64, 8)
void render_kernel(float* __restrict__ out)
{
    __shared__ float4 sP0[CHUNK];
    __shared__ float4 sP1[CHUNK];
    __shared__ float  sFB[CHUNK];

    const int tid = threadIdx.x;
    const int tx  = tid & 7;
    const int ty  = tid >> 3;

    const int tile = blockIdx.y * TX_N + blockIdx.x;
    const int px0 = blockIdx.x * TILE + tx;
    const int py0 = blockIdx.y * TILE + ty;
    const float fx0 = (float)px0;
    const float fy0 = (float)py0;

    const int cnt = g_tile_cnt[tile];

    float a00r = 0.0f, a00g = 0.0f, a00b = 0.0f;   // (x, y)
    float a10r = 0.0f, a10g = 0.0f, a10b = 0.0f;   // (x+8, y)
    float a01r = 0.0f, a01g = 0.0f, a01b = 0.0f;   // (x, y+8)
    float a11r = 0.0f, a11g = 0.0f, a11b = 0.0f;   // (x+8, y+8)

    for (int base = 0; base < cnt; base += CHUNK) {
        int m = cnt - base;
        if (m > CHUNK) m = CHUNK;

        for (int k2 = tid; k2 < m; k2 += 64) {
            int g = g_tile_list[tile][base + k2];
            sP0[k2] = g_P0[g];
            sP1[k2] = g_P1[g];
            sFB[k2] = g_FB[g];
        }
        __syncthreads();

        #pragma unroll 2
        for (int j = 0; j < m; ++j) {
            float4 qa = sP0[j];
            float4 qb = sP1[j];
            float  qc = sFB[j];

            float dx0 = fx0 - qa.x, dx1 = dx0 + 8.0f;
            float dy0 = fy0 - qa.y, dy1 = dy0 + 8.0f;

            float adx0 = qa.z * dx0;                  // A'*dx  (per column)
            float adx1 = qa.z * dx1;
            float rt0  = fmaf(qa.w * dy0, dy0, qb.y); // B'*dy^2 + L' (per row)
            float rt1  = fmaf(qa.w * dy1, dy1, qb.y);

            float t00 = fmaf(qb.x, dy0, adx0);
            float t10 = fmaf(qb.x, dy0, adx1);
            float t01 = fmaf(qb.x, dy1, adx0);
            float t11 = fmaf(qb.x, dy1, adx1);
            float b00 = fmaf(t00, dx0, rt0);
            float b10 = fmaf(t10, dx1, rt0);
            float b01 = fmaf(t01, dx0, rt1);
            float b11 = fmaf(t11, dx1, rt1);

            // e = 2^arg = alpha*255 ; clamp at 0.999*255 ; skip if arg<0 (alpha<1/255)
            float e00, e10, e01, e11;
            asm("ex2.approx.ftz.f32 %0, %1;" : "=f"(e00) : "f"(b00));
            asm("ex2.approx.ftz.f32 %0, %1;" : "=f"(e10) : "f"(b10));
            asm("ex2.approx.ftz.f32 %0, %1;" : "=f"(e01) : "f"(b01));
            asm("ex2.approx.ftz.f32 %0, %1;" : "=f"(e11) : "f"(b11));
            e00 = fminf(e00, E_CAP);
            e10 = fminf(e10, E_CAP);
            e01 = fminf(e01, E_CAP);
            e11 = fminf(e11, E_CAP);

            if (b00 >= 0.0f) {
                a00r = fmaf(e00, qb.z, a00r);
                a00g = fmaf(e00, qb.w, a00g);
                a00b = fmaf(e00, qc,   a00b);
            }
            if (b10 >= 0.0f) {
                a10r = fmaf(e10, qb.z, a10r);
                a10g = fmaf(e10, qb.w, a10g);
                a10b = fmaf(e10, qc,   a10b);
            }
            if (b01 >= 0.0f) {
                a01r = fmaf(e01, qb.z, a01r);
                a01g = fmaf(e01, qb.w, a01g);
                a01b = fmaf(e01, qc,   a01b);
            }
            if (b11 >= 0.0f) {
                a11r = fmaf(e11, qb.z, a11r);
                a11g = fmaf(e11, qb.w, a11g);
                a11b = fmaf(e11, qc,   a11b);
            }
        }
        __syncthreads();
    }

    if (tid == 0) g_tile_cnt[tile] = 0;   // leave zeroed for next launch

    const int px1 = px0 + 8;
    const int py1 = py0 + 8;
    // out layout: [1, 3, H, W]
    out[(0 * H_IMG + py0) * W_IMG + px0] = fminf(fmaxf(a00r, 0.0f), 1.0f);
    out[(0 * H_IMG + py0) * W_IMG + px1] = fminf(fmaxf(a10r, 0.0f), 1.0f);
    out[(0 * H_IMG + py1) * W_IMG + px0] = fminf(fmaxf(a01r, 0.0f), 1.0f);
    out[(0 * H_IMG + py1) * W_IMG + px1] = fminf(fmaxf(a11r, 0.0f), 1.0f);
    out[(1 * H_IMG + py0) * W_IMG + px0] = fminf(fmaxf(a00g, 0.0f), 1.0f);
    out[(1 * H_IMG + py0) * W_IMG + px1] = fminf(fmaxf(a10g, 0.0f), 1.0f);
    out[(1 * H_IMG + py1) * W_IMG + px0] = fminf(fmaxf(a01g, 0.0f), 1.0f);
    out[(1 * H_IMG + py1) * W_IMG + px1] = fminf(fmaxf(a11g, 0.0f), 1.0f);
    out[(2 * H_IMG + py0) * W_IMG + px0] = fminf(fmaxf(a00b, 0.0f), 1.0f);
    out[(2 * H_IMG + py0) * W_IMG + px1] = fminf(fmaxf(a10b, 0.0f), 1.0f);
    out[(2 * H_IMG + py1) * W_IMG + px0] = fminf(fmaxf(a01b, 0.0f), 1.0f);
    out[(2 * H_IMG + py1) * W_IMG + px1] = fminf(fmaxf(a11b, 0.0f), 1.0f);
}

extern "C" void kernel_launch(void* const* d_in, const int* in_sizes, int n_in,
                              void* d_out, int out_size)
{
    const float* xyz     = (const float*)d_in[0];
    const float* scaling = (const float*)d_in[1];
    const float* rot     = (const float*)d_in[2];
    const float* feat    = (const float*)d_in[3];
    const float* opac    = (const float*)d_in[4];
    float* out = (float*)d_out;

    int N = in_sizes[0] / 2;
    if (N > NMAX) N = NMAX;

    // one warp per gaussian
    prep_bin_kernel<<<(N * 32 + 255) / 256, 256>>>(xyz, scaling, rot, feat, opac, N);

    dim3 grid(TX_N, TY_N);
    render_kernel<<<grid, 64>>>(out);
}